// round 1
// baseline (speedup 1.0000x reference)
#include <cuda_runtime.h>

#define NMAX 50000

// Scratch (allocation-free: __device__ globals)
__device__ float g_deg[NMAX];
__device__ float g_dinv[NMAX];
__device__ float g_bufA[(size_t)NMAX * 128];
__device__ float g_bufB[(size_t)NMAX * 128];
__device__ int   g_is64;

// ---------------------------------------------------------------------------
// edge_index dtype detection: reference asks for int64, but default jax config
// downcasts to int32. If int64 (little-endian, values < 2^31), every odd
// 32-bit word is 0. If int32, odd words are random node ids (P(all 0) ~ 0).
// ---------------------------------------------------------------------------
__global__ void detect_dtype_kernel(const int* __restrict__ ei, int nwords) {
    if (blockIdx.x == 0 && threadIdx.x == 0) {
        int nz = 0;
        int lim = nwords < 256 ? nwords : 256;
        for (int i = 1; i < lim; i += 2) nz |= (ei[i] != 0);
        g_is64 = nz ? 0 : 1;
    }
}

__device__ __forceinline__ void load_edge(const void* ei, int E, int e, int& r, int& c) {
    if (g_is64) {
        const long long* p = (const long long*)ei;
        r = (int)p[e];
        c = (int)p[(size_t)E + e];
    } else {
        const int* p = (const int*)ei;
        r = p[e];
        c = p[E + e];
    }
}

// ---------------------------------------------------------------------------
// Degree / normalization
// ---------------------------------------------------------------------------
__global__ void deg_init_kernel(float* deg, int n) {
    int i = blockIdx.x * blockDim.x + threadIdx.x;
    if (i < n) deg[i] = 1.0f;  // self-loop contributes 1
}

__global__ void deg_count_kernel(float* deg, const void* __restrict__ ei, int E) {
    int e = blockIdx.x * blockDim.x + threadIdx.x;
    if (e >= E) return;
    int c;
    if (g_is64) c = (int)((const long long*)ei)[(size_t)E + e];
    else        c = ((const int*)ei)[E + e];
    atomicAdd(&deg[c], 1.0f);
}

__global__ void dinv_kernel(const float* __restrict__ deg, float* dinv, int n) {
    int i = blockIdx.x * blockDim.x + threadIdx.x;
    if (i < n) dinv[i] = rsqrtf(deg[i]);  // deg >= 1 always (self-loops)
}

// agg[i][c] = bias[c]   (128-wide layers only)
__global__ void agg_init_kernel(float* agg, const float* __restrict__ b, int total) {
    int i = blockIdx.x * blockDim.x + threadIdx.x;
    if (i < total) agg[i] = b[i & 127];
}

// ---------------------------------------------------------------------------
// Scatter-aggregate: one warp per (edge | self-loop). 128 feats = 32 lanes x f4.
//   dst[col] += src[row] * dinv[row]*dinv[col]
// ---------------------------------------------------------------------------
__global__ void scatter_kernel(const float* __restrict__ src, float* dst,
                               const void* __restrict__ ei,
                               const float* __restrict__ dinv, int E, int n) {
    int gw   = (blockIdx.x * blockDim.x + threadIdx.x) >> 5;
    int lane = threadIdx.x & 31;
    int EN   = E + n;
    if (gw >= EN) return;
    int r, c;
    if (gw < E) load_edge(ei, E, gw, r, c);
    else        r = c = gw - E;
    float norm = dinv[r] * dinv[c];
    float4 v = ((const float4*)(src + (size_t)r * 128))[lane];
    float* d = dst + (size_t)c * 128 + lane * 4;
    atomicAdd(d + 0, v.x * norm);
    atomicAdd(d + 1, v.y * norm);
    atomicAdd(d + 2, v.z * norm);
    atomicAdd(d + 3, v.w * norm);
}

// ---------------------------------------------------------------------------
// GEMM: C[n][COUT] = (RELU_IN? relu(A) : A)[n][128] @ W[128][COUT] (+ bias)
// W transposed in smem with pad 132 (conflict-free f4), 64 rows/block,
// 4-row chunks -> 4 independent accumulator chains per thread.
// ---------------------------------------------------------------------------
template <int COUT, bool RELU_IN, bool BIAS>
__global__ void gemm_kernel(const float* __restrict__ A, const float* __restrict__ W,
                            const float* __restrict__ bias, float* __restrict__ C, int n) {
    extern __shared__ float smem[];
    float* WsT = smem;                 // [COUT][132]
    float* xs  = smem + COUT * 132;    // [4][128]
    int tid = threadIdx.x;             // 0..COUT-1, one output column per thread

    for (int idx = tid; idx < 128 * COUT; idx += COUT) {
        int k = idx / COUT, c = idx % COUT;
        WsT[c * 132 + k] = W[idx];
    }
    float bv = 0.f;
    if (BIAS) bv = bias[tid];
    __syncthreads();

    int row0 = blockIdx.x * 64;
    const float4* wrow = (const float4*)(WsT + tid * 132);  // 132*4 = 528 B, 16B aligned

    for (int rr = 0; rr < 64; rr += 4) {
        int rbase = row0 + rr;
        if (rbase >= n) return;  // block-uniform exit

        // stage 4 input rows (relu fused here)
        for (int i = tid; i < 128; i += COUT) {
            int r = i >> 5, q = i & 31;
            int gr = rbase + r;
            float4 v = make_float4(0.f, 0.f, 0.f, 0.f);
            if (gr < n) v = ((const float4*)(A + (size_t)gr * 128))[q];
            if (RELU_IN) {
                v.x = fmaxf(v.x, 0.f); v.y = fmaxf(v.y, 0.f);
                v.z = fmaxf(v.z, 0.f); v.w = fmaxf(v.w, 0.f);
            }
            ((float4*)xs)[i] = v;
        }
        __syncthreads();

        float a0 = 0.f, a1 = 0.f, a2 = 0.f, a3 = 0.f;
#pragma unroll
        for (int k4 = 0; k4 < 32; ++k4) {
            float4 w  = wrow[k4];
            float4 x0 = ((const float4*)(xs      ))[k4];
            float4 x1 = ((const float4*)(xs + 128))[k4];
            float4 x2 = ((const float4*)(xs + 256))[k4];
            float4 x3 = ((const float4*)(xs + 384))[k4];
            a0 += w.x * x0.x; a0 += w.y * x0.y; a0 += w.z * x0.z; a0 += w.w * x0.w;
            a1 += w.x * x1.x; a1 += w.y * x1.y; a1 += w.z * x1.z; a1 += w.w * x1.w;
            a2 += w.x * x2.x; a2 += w.y * x2.y; a2 += w.z * x2.z; a2 += w.w * x2.w;
            a3 += w.x * x3.x; a3 += w.y * x3.y; a3 += w.z * x3.z; a3 += w.w * x3.w;
        }
        if (BIAS) { a0 += bv; a1 += bv; a2 += bv; a3 += bv; }

        if (rbase + 0 < n) C[(size_t)(rbase + 0) * COUT + tid] = a0;
        if (rbase + 1 < n) C[(size_t)(rbase + 1) * COUT + tid] = a1;
        if (rbase + 2 < n) C[(size_t)(rbase + 2) * COUT + tid] = a2;
        if (rbase + 3 < n) C[(size_t)(rbase + 3) * COUT + tid] = a3;
        __syncthreads();
    }
}

// ---------------------------------------------------------------------------
// Launch. Inputs: x, edge_index, W1, b1, W2, b2, Wl, bl. Output: [n, 64] f32.
// ---------------------------------------------------------------------------
extern "C" void kernel_launch(void* const* d_in, const int* in_sizes, int n_in,
                              void* d_out, int out_size) {
    const float* x  = (const float*)d_in[0];
    const void*  ei = d_in[1];
    const float* W1 = (const float*)d_in[2];
    const float* b1 = (const float*)d_in[3];
    const float* W2 = (const float*)d_in[4];
    const float* b2 = (const float*)d_in[5];
    const float* Wl = (const float*)d_in[6];
    const float* bl = (const float*)d_in[7];
    float* out = (float*)d_out;

    int n = in_sizes[0] / 128;   // 50000
    int E = in_sizes[1] / 2;     // 640000 (element count is dtype-independent)

    float *deg, *dinv, *bufA, *bufB;
    cudaGetSymbolAddress((void**)&deg,  g_deg);
    cudaGetSymbolAddress((void**)&dinv, g_dinv);
    cudaGetSymbolAddress((void**)&bufA, g_bufA);
    cudaGetSymbolAddress((void**)&bufB, g_bufB);

    const size_t smem128 = 128 * 132 * sizeof(float) + 4 * 128 * sizeof(float); // 69632
    const size_t smem64  =  64 * 132 * sizeof(float) + 4 * 128 * sizeof(float); // 35840
    cudaFuncSetAttribute(gemm_kernel<128, false, false>,
                         cudaFuncAttributeMaxDynamicSharedMemorySize, (int)smem128);
    cudaFuncSetAttribute(gemm_kernel<128, true, false>,
                         cudaFuncAttributeMaxDynamicSharedMemorySize, (int)smem128);
    cudaFuncSetAttribute(gemm_kernel<64, true, true>,
                         cudaFuncAttributeMaxDynamicSharedMemorySize, (int)smem64);

    int nb256 = (n + 255) / 256;
    detect_dtype_kernel<<<1, 32>>>((const int*)ei, 256);
    deg_init_kernel<<<nb256, 256>>>(deg, n);
    deg_count_kernel<<<(E + 255) / 256, 256>>>(deg, ei, E);
    dinv_kernel<<<nb256, 256>>>(deg, dinv, n);

    int gemm_blocks = (n + 63) / 64;
    int EN = E + n;
    int scat_blocks = (EN + 7) / 8;       // 8 warps per 256-thread block
    int init_blocks = (n * 128 + 255) / 256;

    // Layer 1: h1 = relu( Agg(x @ W1) + b1 )   (relu fused into next gemm load)
    gemm_kernel<128, false, false><<<gemm_blocks, 128, smem128>>>(x, W1, nullptr, bufA, n);
    agg_init_kernel<<<init_blocks, 256>>>(bufB, b1, n * 128);
    scatter_kernel<<<scat_blocks, 256>>>(bufA, bufB, ei, dinv, E, n);

    // Layer 2: h2 = relu( Agg(relu(h1) @ W2) + b2 )
    gemm_kernel<128, true, false><<<gemm_blocks, 128, smem128>>>(bufB, W2, nullptr, bufA, n);
    agg_init_kernel<<<init_blocks, 256>>>(bufB, b2, n * 128);
    scatter_kernel<<<scat_blocks, 256>>>(bufA, bufB, ei, dinv, E, n);

    // Head: out = relu(h2) @ Wl + bl
    gemm_kernel<64, true, true><<<gemm_blocks, 64, smem64>>>(bufB, Wl, bl, out, n);
}

// round 2
// speedup vs baseline: 1.0015x; 1.0015x over previous
#include <cuda_runtime.h>

#define NMAX 50000

// Scratch (allocation-free: __device__ globals)
__device__ float g_deg[NMAX];
__device__ float g_dinv[NMAX];
__device__ float g_bufA[(size_t)NMAX * 128];
__device__ float g_bufB[(size_t)NMAX * 128];
__device__ int   g_is64;

// ---------------------------------------------------------------------------
// edge_index dtype detection: reference asks for int64, but default jax config
// downcasts to int32. If int64 (little-endian, values < 2^31), every odd
// 32-bit word is 0. If int32, odd words are random node ids (P(all 0) ~ 0).
// ---------------------------------------------------------------------------
__global__ void detect_dtype_kernel(const int* __restrict__ ei, int nwords) {
    if (blockIdx.x == 0 && threadIdx.x == 0) {
        int nz = 0;
        int lim = nwords < 256 ? nwords : 256;
        for (int i = 1; i < lim; i += 2) nz |= (ei[i] != 0);
        g_is64 = nz ? 0 : 1;
    }
}

__device__ __forceinline__ void load_edge(const void* ei, int E, int e, int& r, int& c) {
    if (g_is64) {
        const long long* p = (const long long*)ei;
        r = (int)p[e];
        c = (int)p[(size_t)E + e];
    } else {
        const int* p = (const int*)ei;
        r = p[e];
        c = p[E + e];
    }
}

// ---------------------------------------------------------------------------
// Degree / normalization
// ---------------------------------------------------------------------------
__global__ void deg_init_kernel(float* deg, int n) {
    int i = blockIdx.x * blockDim.x + threadIdx.x;
    if (i < n) deg[i] = 1.0f;  // self-loop contributes 1
}

__global__ void deg_count_kernel(float* deg, const void* __restrict__ ei, int E) {
    int e = blockIdx.x * blockDim.x + threadIdx.x;
    if (e >= E) return;
    int c;
    if (g_is64) c = (int)((const long long*)ei)[(size_t)E + e];
    else        c = ((const int*)ei)[E + e];
    atomicAdd(&deg[c], 1.0f);
}

__global__ void dinv_kernel(const float* __restrict__ deg, float* dinv, int n) {
    int i = blockIdx.x * blockDim.x + threadIdx.x;
    if (i < n) dinv[i] = rsqrtf(deg[i]);  // deg >= 1 always (self-loops)
}

// agg[i][c] = bias[c]   (128-wide layers only)
__global__ void agg_init_kernel(float* agg, const float* __restrict__ b, int total) {
    int i = blockIdx.x * blockDim.x + threadIdx.x;
    if (i < total) agg[i] = b[i & 127];
}

// ---------------------------------------------------------------------------
// Scatter-aggregate: one warp per (edge | self-loop). 128 feats = 32 lanes x f4.
//   dst[col] += src[row] * dinv[row]*dinv[col]
// ---------------------------------------------------------------------------
__global__ void scatter_kernel(const float* __restrict__ src, float* dst,
                               const void* __restrict__ ei,
                               const float* __restrict__ dinv, int E, int n) {
    int gw   = (blockIdx.x * blockDim.x + threadIdx.x) >> 5;
    int lane = threadIdx.x & 31;
    int EN   = E + n;
    if (gw >= EN) return;
    int r, c;
    if (gw < E) load_edge(ei, E, gw, r, c);
    else        r = c = gw - E;
    float norm = dinv[r] * dinv[c];
    float4 v = ((const float4*)(src + (size_t)r * 128))[lane];
    float* d = dst + (size_t)c * 128 + lane * 4;
    atomicAdd(d + 0, v.x * norm);
    atomicAdd(d + 1, v.y * norm);
    atomicAdd(d + 2, v.z * norm);
    atomicAdd(d + 3, v.w * norm);
}

// ---------------------------------------------------------------------------
// GEMM: C[n][COUT] = (RELU_IN? relu(A) : A)[n][128] @ W[128][COUT] (+ bias)
// W transposed in smem with pad 132 (conflict-free f4), 64 rows/block,
// 4-row chunks -> 4 independent accumulator chains per thread.
// ---------------------------------------------------------------------------
template <int COUT, bool RELU_IN, bool BIAS>
__global__ void gemm_kernel(const float* __restrict__ A, const float* __restrict__ W,
                            const float* __restrict__ bias, float* __restrict__ C, int n) {
    extern __shared__ float smem[];
    float* WsT = smem;                 // [COUT][132]
    float* xs  = smem + COUT * 132;    // [4][128]
    int tid = threadIdx.x;             // 0..COUT-1, one output column per thread

    for (int idx = tid; idx < 128 * COUT; idx += COUT) {
        int k = idx / COUT, c = idx % COUT;
        WsT[c * 132 + k] = W[idx];
    }
    float bv = 0.f;
    if (BIAS) bv = bias[tid];
    __syncthreads();

    int row0 = blockIdx.x * 64;
    const float4* wrow = (const float4*)(WsT + tid * 132);  // 132*4 = 528 B, 16B aligned

    for (int rr = 0; rr < 64; rr += 4) {
        int rbase = row0 + rr;
        if (rbase >= n) return;  // block-uniform exit

        // stage 4 input rows (relu fused here)
        for (int i = tid; i < 128; i += COUT) {
            int r = i >> 5, q = i & 31;
            int gr = rbase + r;
            float4 v = make_float4(0.f, 0.f, 0.f, 0.f);
            if (gr < n) v = ((const float4*)(A + (size_t)gr * 128))[q];
            if (RELU_IN) {
                v.x = fmaxf(v.x, 0.f); v.y = fmaxf(v.y, 0.f);
                v.z = fmaxf(v.z, 0.f); v.w = fmaxf(v.w, 0.f);
            }
            ((float4*)xs)[i] = v;
        }
        __syncthreads();

        float a0 = 0.f, a1 = 0.f, a2 = 0.f, a3 = 0.f;
#pragma unroll
        for (int k4 = 0; k4 < 32; ++k4) {
            float4 w  = wrow[k4];
            float4 x0 = ((const float4*)(xs      ))[k4];
            float4 x1 = ((const float4*)(xs + 128))[k4];
            float4 x2 = ((const float4*)(xs + 256))[k4];
            float4 x3 = ((const float4*)(xs + 384))[k4];
            a0 += w.x * x0.x; a0 += w.y * x0.y; a0 += w.z * x0.z; a0 += w.w * x0.w;
            a1 += w.x * x1.x; a1 += w.y * x1.y; a1 += w.z * x1.z; a1 += w.w * x1.w;
            a2 += w.x * x2.x; a2 += w.y * x2.y; a2 += w.z * x2.z; a2 += w.w * x2.w;
            a3 += w.x * x3.x; a3 += w.y * x3.y; a3 += w.z * x3.z; a3 += w.w * x3.w;
        }
        if (BIAS) { a0 += bv; a1 += bv; a2 += bv; a3 += bv; }

        if (rbase + 0 < n) C[(size_t)(rbase + 0) * COUT + tid] = a0;
        if (rbase + 1 < n) C[(size_t)(rbase + 1) * COUT + tid] = a1;
        if (rbase + 2 < n) C[(size_t)(rbase + 2) * COUT + tid] = a2;
        if (rbase + 3 < n) C[(size_t)(rbase + 3) * COUT + tid] = a3;
        __syncthreads();
    }
}

// ---------------------------------------------------------------------------
// Launch. Inputs: x, edge_index, W1, b1, W2, b2, Wl, bl. Output: [n, 64] f32.
// ---------------------------------------------------------------------------
extern "C" void kernel_launch(void* const* d_in, const int* in_sizes, int n_in,
                              void* d_out, int out_size) {
    const float* x  = (const float*)d_in[0];
    const void*  ei = d_in[1];
    const float* W1 = (const float*)d_in[2];
    const float* b1 = (const float*)d_in[3];
    const float* W2 = (const float*)d_in[4];
    const float* b2 = (const float*)d_in[5];
    const float* Wl = (const float*)d_in[6];
    const float* bl = (const float*)d_in[7];
    float* out = (float*)d_out;

    int n = in_sizes[0] / 128;   // 50000
    int E = in_sizes[1] / 2;     // 640000 (element count is dtype-independent)

    float *deg, *dinv, *bufA, *bufB;
    cudaGetSymbolAddress((void**)&deg,  g_deg);
    cudaGetSymbolAddress((void**)&dinv, g_dinv);
    cudaGetSymbolAddress((void**)&bufA, g_bufA);
    cudaGetSymbolAddress((void**)&bufB, g_bufB);

    const size_t smem128 = 128 * 132 * sizeof(float) + 4 * 128 * sizeof(float); // 69632
    const size_t smem64  =  64 * 132 * sizeof(float) + 4 * 128 * sizeof(float); // 35840
    cudaFuncSetAttribute(gemm_kernel<128, false, false>,
                         cudaFuncAttributeMaxDynamicSharedMemorySize, (int)smem128);
    cudaFuncSetAttribute(gemm_kernel<128, true, false>,
                         cudaFuncAttributeMaxDynamicSharedMemorySize, (int)smem128);
    cudaFuncSetAttribute(gemm_kernel<64, true, true>,
                         cudaFuncAttributeMaxDynamicSharedMemorySize, (int)smem64);

    int nb256 = (n + 255) / 256;
    detect_dtype_kernel<<<1, 32>>>((const int*)ei, 256);
    deg_init_kernel<<<nb256, 256>>>(deg, n);
    deg_count_kernel<<<(E + 255) / 256, 256>>>(deg, ei, E);
    dinv_kernel<<<nb256, 256>>>(deg, dinv, n);

    int gemm_blocks = (n + 63) / 64;
    int EN = E + n;
    int scat_blocks = (EN + 7) / 8;       // 8 warps per 256-thread block
    int init_blocks = (n * 128 + 255) / 256;

    // Layer 1: h1 = relu( Agg(x @ W1) + b1 )   (relu fused into next gemm load)
    gemm_kernel<128, false, false><<<gemm_blocks, 128, smem128>>>(x, W1, nullptr, bufA, n);
    agg_init_kernel<<<init_blocks, 256>>>(bufB, b1, n * 128);
    scatter_kernel<<<scat_blocks, 256>>>(bufA, bufB, ei, dinv, E, n);

    // Layer 2: h2 = relu( Agg(relu(h1) @ W2) + b2 )
    gemm_kernel<128, true, false><<<gemm_blocks, 128, smem128>>>(bufB, W2, nullptr, bufA, n);
    agg_init_kernel<<<init_blocks, 256>>>(bufB, b2, n * 128);
    scatter_kernel<<<scat_blocks, 256>>>(bufA, bufB, ei, dinv, E, n);

    // Head: out = relu(h2) @ Wl + bl
    gemm_kernel<64, true, true><<<gemm_blocks, 64, smem64>>>(bufB, Wl, bl, out, n);
}

// round 3
// speedup vs baseline: 1.4828x; 1.4806x over previous
#include <cuda_runtime.h>

#define NMAX 50000

// Scratch (allocation-free: __device__ globals)
__device__ float g_deg[NMAX];
__device__ float g_dinv[NMAX];
__device__ float g_bufA[(size_t)NMAX * 128];
__device__ float g_bufB[(size_t)NMAX * 128];
__device__ int   g_is64;

// ---------------------------------------------------------------------------
// edge_index dtype detection: reference asks for int64, but default jax config
// downcasts to int32. If int64 (little-endian, values < 2^31), every odd
// 32-bit word is 0. If int32, odd words are random node ids (P(all 0) ~ 0).
// ---------------------------------------------------------------------------
__global__ void detect_dtype_kernel(const int* __restrict__ ei, int nwords) {
    if (blockIdx.x == 0 && threadIdx.x == 0) {
        int nz = 0;
        int lim = nwords < 256 ? nwords : 256;
        for (int i = 1; i < lim; i += 2) nz |= (ei[i] != 0);
        g_is64 = nz ? 0 : 1;
    }
}

__device__ __forceinline__ void load_edge(const void* ei, int E, int e, int& r, int& c) {
    if (g_is64) {
        const long long* p = (const long long*)ei;
        r = (int)p[e];
        c = (int)p[(size_t)E + e];
    } else {
        const int* p = (const int*)ei;
        r = p[e];
        c = p[E + e];
    }
}

// ---------------------------------------------------------------------------
// Degree / normalization
// ---------------------------------------------------------------------------
__global__ void deg_init_kernel(float* deg, int n) {
    int i = blockIdx.x * blockDim.x + threadIdx.x;
    if (i < n) deg[i] = 1.0f;  // self-loop contributes 1
}

__global__ void deg_count_kernel(float* deg, const void* __restrict__ ei, int E) {
    int e = blockIdx.x * blockDim.x + threadIdx.x;
    if (e >= E) return;
    int c;
    if (g_is64) c = (int)((const long long*)ei)[(size_t)E + e];
    else        c = ((const int*)ei)[E + e];
    atomicAdd(&deg[c], 1.0f);
}

__global__ void dinv_kernel(const float* __restrict__ deg, float* dinv, int n) {
    int i = blockIdx.x * blockDim.x + threadIdx.x;
    if (i < n) dinv[i] = rsqrtf(deg[i]);  // deg >= 1 always (self-loops)
}

// agg[i][c] = bias[c]   (128-wide layers only)
__global__ void agg_init_kernel(float* agg, const float* __restrict__ b, int total) {
    int i = blockIdx.x * blockDim.x + threadIdx.x;
    if (i < total) agg[i] = b[i & 127];
}

// ---------------------------------------------------------------------------
// Scatter-aggregate: one warp per (edge | self-loop). 128 feats = 32 lanes x f4.
//   dst[col] += src[row] * dinv[row]*dinv[col]
// One red.global.add.v4.f32 per lane (16B vector reduction, sm_90+) instead of
// 4 scalar atomics -> 4x fewer L2 atomic ops (the LTS atomic-ALU is the
// serialization point at ~1 op/LTS/cycle).
// ---------------------------------------------------------------------------
__global__ void scatter_kernel(const float* __restrict__ src, float* dst,
                               const void* __restrict__ ei,
                               const float* __restrict__ dinv, int E, int n) {
    int gw   = (blockIdx.x * blockDim.x + threadIdx.x) >> 5;
    int lane = threadIdx.x & 31;
    int EN   = E + n;
    if (gw >= EN) return;
    int r, c;
    if (gw < E) load_edge(ei, E, gw, r, c);
    else        r = c = gw - E;
    float norm = dinv[r] * dinv[c];
    float4 v = ((const float4*)(src + (size_t)r * 128))[lane];
    float* d = dst + (size_t)c * 128 + lane * 4;
    asm volatile("red.global.add.v4.f32 [%0], {%1, %2, %3, %4};"
                 :: "l"(d), "f"(v.x * norm), "f"(v.y * norm),
                    "f"(v.z * norm), "f"(v.w * norm)
                 : "memory");
}

// ---------------------------------------------------------------------------
// GEMM: C[n][COUT] = (RELU_IN? relu(A) : A)[n][128] @ W[128][COUT] (+ bias)
// W transposed in smem with pad 132 (conflict-free f4), 64 rows/block,
// 4-row chunks -> 4 independent accumulator chains per thread.
// ---------------------------------------------------------------------------
template <int COUT, bool RELU_IN, bool BIAS>
__global__ void gemm_kernel(const float* __restrict__ A, const float* __restrict__ W,
                            const float* __restrict__ bias, float* __restrict__ C, int n) {
    extern __shared__ float smem[];
    float* WsT = smem;                 // [COUT][132]
    float* xs  = smem + COUT * 132;    // [4][128]
    int tid = threadIdx.x;             // 0..COUT-1, one output column per thread

    for (int idx = tid; idx < 128 * COUT; idx += COUT) {
        int k = idx / COUT, c = idx % COUT;
        WsT[c * 132 + k] = W[idx];
    }
    float bv = 0.f;
    if (BIAS) bv = bias[tid];
    __syncthreads();

    int row0 = blockIdx.x * 64;
    const float4* wrow = (const float4*)(WsT + tid * 132);  // 132*4 = 528 B, 16B aligned

    for (int rr = 0; rr < 64; rr += 4) {
        int rbase = row0 + rr;
        if (rbase >= n) return;  // block-uniform exit

        // stage 4 input rows (relu fused here)
        for (int i = tid; i < 128; i += COUT) {
            int r = i >> 5, q = i & 31;
            int gr = rbase + r;
            float4 v = make_float4(0.f, 0.f, 0.f, 0.f);
            if (gr < n) v = ((const float4*)(A + (size_t)gr * 128))[q];
            if (RELU_IN) {
                v.x = fmaxf(v.x, 0.f); v.y = fmaxf(v.y, 0.f);
                v.z = fmaxf(v.z, 0.f); v.w = fmaxf(v.w, 0.f);
            }
            ((float4*)xs)[i] = v;
        }
        __syncthreads();

        float a0 = 0.f, a1 = 0.f, a2 = 0.f, a3 = 0.f;
#pragma unroll
        for (int k4 = 0; k4 < 32; ++k4) {
            float4 w  = wrow[k4];
            float4 x0 = ((const float4*)(xs      ))[k4];
            float4 x1 = ((const float4*)(xs + 128))[k4];
            float4 x2 = ((const float4*)(xs + 256))[k4];
            float4 x3 = ((const float4*)(xs + 384))[k4];
            a0 += w.x * x0.x; a0 += w.y * x0.y; a0 += w.z * x0.z; a0 += w.w * x0.w;
            a1 += w.x * x1.x; a1 += w.y * x1.y; a1 += w.z * x1.z; a1 += w.w * x1.w;
            a2 += w.x * x2.x; a2 += w.y * x2.y; a2 += w.z * x2.z; a2 += w.w * x2.w;
            a3 += w.x * x3.x; a3 += w.y * x3.y; a3 += w.z * x3.z; a3 += w.w * x3.w;
        }
        if (BIAS) { a0 += bv; a1 += bv; a2 += bv; a3 += bv; }

        if (rbase + 0 < n) C[(size_t)(rbase + 0) * COUT + tid] = a0;
        if (rbase + 1 < n) C[(size_t)(rbase + 1) * COUT + tid] = a1;
        if (rbase + 2 < n) C[(size_t)(rbase + 2) * COUT + tid] = a2;
        if (rbase + 3 < n) C[(size_t)(rbase + 3) * COUT + tid] = a3;
        __syncthreads();
    }
}

// ---------------------------------------------------------------------------
// Launch. Inputs: x, edge_index, W1, b1, W2, b2, Wl, bl. Output: [n, 64] f32.
// ---------------------------------------------------------------------------
extern "C" void kernel_launch(void* const* d_in, const int* in_sizes, int n_in,
                              void* d_out, int out_size) {
    const float* x  = (const float*)d_in[0];
    const void*  ei = d_in[1];
    const float* W1 = (const float*)d_in[2];
    const float* b1 = (const float*)d_in[3];
    const float* W2 = (const float*)d_in[4];
    const float* b2 = (const float*)d_in[5];
    const float* Wl = (const float*)d_in[6];
    const float* bl = (const float*)d_in[7];
    float* out = (float*)d_out;

    int n = in_sizes[0] / 128;   // 50000
    int E = in_sizes[1] / 2;     // 640000 (element count is dtype-independent)

    float *deg, *dinv, *bufA, *bufB;
    cudaGetSymbolAddress((void**)&deg,  g_deg);
    cudaGetSymbolAddress((void**)&dinv, g_dinv);
    cudaGetSymbolAddress((void**)&bufA, g_bufA);
    cudaGetSymbolAddress((void**)&bufB, g_bufB);

    const size_t smem128 = 128 * 132 * sizeof(float) + 4 * 128 * sizeof(float); // 69632
    const size_t smem64  =  64 * 132 * sizeof(float) + 4 * 128 * sizeof(float); // 35840
    cudaFuncSetAttribute(gemm_kernel<128, false, false>,
                         cudaFuncAttributeMaxDynamicSharedMemorySize, (int)smem128);
    cudaFuncSetAttribute(gemm_kernel<128, true, false>,
                         cudaFuncAttributeMaxDynamicSharedMemorySize, (int)smem128);
    cudaFuncSetAttribute(gemm_kernel<64, true, true>,
                         cudaFuncAttributeMaxDynamicSharedMemorySize, (int)smem64);

    int nb256 = (n + 255) / 256;
    detect_dtype_kernel<<<1, 32>>>((const int*)ei, 256);
    deg_init_kernel<<<nb256, 256>>>(deg, n);
    deg_count_kernel<<<(E + 255) / 256, 256>>>(deg, ei, E);
    dinv_kernel<<<nb256, 256>>>(deg, dinv, n);

    int gemm_blocks = (n + 63) / 64;
    int EN = E + n;
    int scat_blocks = (EN + 7) / 8;       // 8 warps per 256-thread block
    int init_blocks = (n * 128 + 255) / 256;

    // Layer 1: h1 = relu( Agg(x @ W1) + b1 )   (relu fused into next gemm load)
    gemm_kernel<128, false, false><<<gemm_blocks, 128, smem128>>>(x, W1, nullptr, bufA, n);
    agg_init_kernel<<<init_blocks, 256>>>(bufB, b1, n * 128);
    scatter_kernel<<<scat_blocks, 256>>>(bufA, bufB, ei, dinv, E, n);

    // Layer 2: h2 = relu( Agg(relu(h1) @ W2) + b2 )
    gemm_kernel<128, true, false><<<gemm_blocks, 128, smem128>>>(bufB, W2, nullptr, bufA, n);
    agg_init_kernel<<<init_blocks, 256>>>(bufB, b2, n * 128);
    scatter_kernel<<<scat_blocks, 256>>>(bufA, bufB, ei, dinv, E, n);

    // Head: out = relu(h2) @ Wl + bl
    gemm_kernel<64, true, true><<<gemm_blocks, 64, smem64>>>(bufB, Wl, bl, out, n);
}

// round 4
// speedup vs baseline: 1.8784x; 1.2668x over previous
#include <cuda_runtime.h>

#define NMAX 50000
#define EMAX 700000

// Scratch (allocation-free: __device__ globals)
__device__ float g_dinv[NMAX];
__device__ float g_bufA[(size_t)NMAX * 128];
__device__ float g_bufB[(size_t)NMAX * 128];
__device__ int   g_cnt[NMAX];
__device__ int   g_incl[NMAX];
__device__ int   g_bsum[256];
__device__ int   g_off[NMAX + 1];
__device__ int   g_cursor[NMAX];
__device__ int   g_srcid[EMAX];
__device__ int   g_is64;

// ---------------------------------------------------------------------------
// edge_index dtype detection: reference asks for int64, but default jax config
// downcasts to int32. If int64 (little-endian, values < 2^31), every odd
// 32-bit word is 0. If int32, odd words are random node ids.
// ---------------------------------------------------------------------------
__global__ void detect_dtype_kernel(const int* __restrict__ ei) {
    if (threadIdx.x == 0) {
        int nz = 0;
        for (int i = 1; i < 256; i += 2) nz |= (ei[i] != 0);
        g_is64 = nz ? 0 : 1;
    }
}

__device__ __forceinline__ void load_edge(const void* ei, int E, int e, int& r, int& c) {
    if (g_is64) {
        const long long* p = (const long long*)ei;
        r = (int)p[e];
        c = (int)p[(size_t)E + e];
    } else {
        const int* p = (const int*)ei;
        r = p[e];
        c = p[E + e];
    }
}

// ---------------------------------------------------------------------------
// CSR build: counting sort of edges by destination (col), self-loops included.
// ---------------------------------------------------------------------------
__global__ void cnt_init_kernel(int* cnt, int n) {
    int i = blockIdx.x * blockDim.x + threadIdx.x;
    if (i < n) cnt[i] = 1;  // self-loop
}

__global__ void cnt_count_kernel(int* cnt, const void* __restrict__ ei, int E) {
    int e = blockIdx.x * blockDim.x + threadIdx.x;
    if (e >= E) return;
    int c;
    if (g_is64) c = (int)((const long long*)ei)[(size_t)E + e];
    else        c = ((const int*)ei)[E + e];
    atomicAdd(&cnt[c], 1);
}

// block-local inclusive scan (256 wide) + block sums
__global__ void scan1_kernel(const int* __restrict__ cnt, int* incl, int* bsum, int n) {
    __shared__ int s[256];
    int i = blockIdx.x * 256 + threadIdx.x;
    int v = (i < n) ? cnt[i] : 0;
    s[threadIdx.x] = v;
    __syncthreads();
#pragma unroll
    for (int d = 1; d < 256; d <<= 1) {
        int t = (threadIdx.x >= d) ? s[threadIdx.x - d] : 0;
        __syncthreads();
        s[threadIdx.x] += t;
        __syncthreads();
    }
    if (i < n) incl[i] = s[threadIdx.x];
    if (threadIdx.x == 255) bsum[blockIdx.x] = s[255];
}

// exclusive scan of block sums (nb <= 256), single block
__global__ void scan2_kernel(int* bsum, int nb) {
    __shared__ int s[256];
    int v = (threadIdx.x < nb) ? bsum[threadIdx.x] : 0;
    s[threadIdx.x] = v;
    __syncthreads();
#pragma unroll
    for (int d = 1; d < 256; d <<= 1) {
        int t = (threadIdx.x >= d) ? s[threadIdx.x - d] : 0;
        __syncthreads();
        s[threadIdx.x] += t;
        __syncthreads();
    }
    if (threadIdx.x < nb) bsum[threadIdx.x] = s[threadIdx.x] - v;  // exclusive
}

// finalize offsets, cursors, and dinv (deg = cnt, >= 1 via self-loop)
__global__ void scan3_kernel(const int* __restrict__ incl, const int* __restrict__ bsum,
                             const int* __restrict__ cnt, int* off, int* cursor,
                             float* dinv, int n) {
    int i = blockIdx.x * blockDim.x + threadIdx.x;
    if (i >= n) return;
    int v = incl[i] + bsum[i >> 8];
    off[i + 1] = v;
    cursor[i]  = v - cnt[i];
    dinv[i]    = rsqrtf((float)cnt[i]);
    if (i == 0) off[0] = 0;
}

__global__ void fill_kernel(int* cursor, int* srcid, const void* __restrict__ ei,
                            int E, int n) {
    int e = blockIdx.x * blockDim.x + threadIdx.x;
    if (e >= E + n) return;
    int r, c;
    if (e < E) load_edge(ei, E, e, r, c);
    else       r = c = e - E;
    int p = atomicAdd(&cursor[c], 1);
    srcid[p] = r;
}

// ---------------------------------------------------------------------------
// Gather-aggregate (no atomics): one warp per destination node.
//   dst[c] = bias + dinv[c] * sum_{r in N(c)} dinv[r] * src[r]
// Edge ids + source norms are lane-prefetched and shfl-broadcast.
// ---------------------------------------------------------------------------
__global__ void gather_kernel(const float* __restrict__ A, float* __restrict__ dst,
                              const int* __restrict__ srcid, const int* __restrict__ off,
                              const float* __restrict__ dinv,
                              const float* __restrict__ bias, int n) {
    int c    = (blockIdx.x * blockDim.x + threadIdx.x) >> 5;
    int lane = threadIdx.x & 31;
    if (c >= n) return;
    int s = off[c], e = off[c + 1];
    float dc = dinv[c];

    float sx = 0.f, sy = 0.f, sz = 0.f, sw = 0.f;
    const float4* A4 = (const float4*)A;

    for (int base = s; base < e; base += 32) {
        int idx = base + lane;
        int r   = 0;
        float dr = 0.f;
        if (idx < e) { r = srcid[idx]; dr = dinv[r]; }
        int m = min(32, e - base);
        for (int k = 0; k < m; ++k) {
            int   rk  = __shfl_sync(0xffffffffu, r, k);
            float drk = __shfl_sync(0xffffffffu, dr, k);
            float4 v  = A4[(size_t)rk * 32 + lane];
            sx += drk * v.x; sy += drk * v.y;
            sz += drk * v.z; sw += drk * v.w;
        }
    }
    float4 b = ((const float4*)bias)[lane];
    float4 o;
    o.x = b.x + dc * sx; o.y = b.y + dc * sy;
    o.z = b.z + dc * sz; o.w = b.w + dc * sw;
    ((float4*)dst)[(size_t)c * 32 + lane] = o;
}

// ---------------------------------------------------------------------------
// GEMM: C[n][COUT] = (RELU_IN? relu(A) : A)[n][128] @ W[128][COUT] (+ bias)
// ---------------------------------------------------------------------------
template <int COUT, bool RELU_IN, bool BIAS>
__global__ void gemm_kernel(const float* __restrict__ A, const float* __restrict__ W,
                            const float* __restrict__ bias, float* __restrict__ C, int n) {
    extern __shared__ float smem[];
    float* WsT = smem;                 // [COUT][132]
    float* xs  = smem + COUT * 132;    // [4][128]
    int tid = threadIdx.x;             // one output column per thread

    for (int idx = tid; idx < 128 * COUT; idx += COUT) {
        int k = idx / COUT, c = idx % COUT;
        WsT[c * 132 + k] = W[idx];
    }
    float bv = 0.f;
    if (BIAS) bv = bias[tid];
    __syncthreads();

    int row0 = blockIdx.x * 64;
    const float4* wrow = (const float4*)(WsT + tid * 132);

    for (int rr = 0; rr < 64; rr += 4) {
        int rbase = row0 + rr;
        if (rbase >= n) return;

        for (int i = tid; i < 128; i += COUT) {
            int r = i >> 5, q = i & 31;
            int gr = rbase + r;
            float4 v = make_float4(0.f, 0.f, 0.f, 0.f);
            if (gr < n) v = ((const float4*)(A + (size_t)gr * 128))[q];
            if (RELU_IN) {
                v.x = fmaxf(v.x, 0.f); v.y = fmaxf(v.y, 0.f);
                v.z = fmaxf(v.z, 0.f); v.w = fmaxf(v.w, 0.f);
            }
            ((float4*)xs)[i] = v;
        }
        __syncthreads();

        float a0 = 0.f, a1 = 0.f, a2 = 0.f, a3 = 0.f;
#pragma unroll
        for (int k4 = 0; k4 < 32; ++k4) {
            float4 w  = wrow[k4];
            float4 x0 = ((const float4*)(xs      ))[k4];
            float4 x1 = ((const float4*)(xs + 128))[k4];
            float4 x2 = ((const float4*)(xs + 256))[k4];
            float4 x3 = ((const float4*)(xs + 384))[k4];
            a0 += w.x * x0.x; a0 += w.y * x0.y; a0 += w.z * x0.z; a0 += w.w * x0.w;
            a1 += w.x * x1.x; a1 += w.y * x1.y; a1 += w.z * x1.z; a1 += w.w * x1.w;
            a2 += w.x * x2.x; a2 += w.y * x2.y; a2 += w.z * x2.z; a2 += w.w * x2.w;
            a3 += w.x * x3.x; a3 += w.y * x3.y; a3 += w.z * x3.z; a3 += w.w * x3.w;
        }
        if (BIAS) { a0 += bv; a1 += bv; a2 += bv; a3 += bv; }

        if (rbase + 0 < n) C[(size_t)(rbase + 0) * COUT + tid] = a0;
        if (rbase + 1 < n) C[(size_t)(rbase + 1) * COUT + tid] = a1;
        if (rbase + 2 < n) C[(size_t)(rbase + 2) * COUT + tid] = a2;
        if (rbase + 3 < n) C[(size_t)(rbase + 3) * COUT + tid] = a3;
        __syncthreads();
    }
}

// ---------------------------------------------------------------------------
// Launch. Inputs: x, edge_index, W1, b1, W2, b2, Wl, bl. Output: [n, 64] f32.
// ---------------------------------------------------------------------------
extern "C" void kernel_launch(void* const* d_in, const int* in_sizes, int n_in,
                              void* d_out, int out_size) {
    const float* x  = (const float*)d_in[0];
    const void*  ei = d_in[1];
    const float* W1 = (const float*)d_in[2];
    const float* b1 = (const float*)d_in[3];
    const float* W2 = (const float*)d_in[4];
    const float* b2 = (const float*)d_in[5];
    const float* Wl = (const float*)d_in[6];
    const float* bl = (const float*)d_in[7];
    float* out = (float*)d_out;

    int n = in_sizes[0] / 128;   // 50000
    int E = in_sizes[1] / 2;     // 640000

    float *dinv, *bufA, *bufB;
    int *cnt, *incl, *bsum, *off, *cursor, *srcid;
    cudaGetSymbolAddress((void**)&dinv,   g_dinv);
    cudaGetSymbolAddress((void**)&bufA,   g_bufA);
    cudaGetSymbolAddress((void**)&bufB,   g_bufB);
    cudaGetSymbolAddress((void**)&cnt,    g_cnt);
    cudaGetSymbolAddress((void**)&incl,   g_incl);
    cudaGetSymbolAddress((void**)&bsum,   g_bsum);
    cudaGetSymbolAddress((void**)&off,    g_off);
    cudaGetSymbolAddress((void**)&cursor, g_cursor);
    cudaGetSymbolAddress((void**)&srcid,  g_srcid);

    const size_t smem128 = 128 * 132 * sizeof(float) + 4 * 128 * sizeof(float);
    const size_t smem64  =  64 * 132 * sizeof(float) + 4 * 128 * sizeof(float);
    cudaFuncSetAttribute(gemm_kernel<128, false, false>,
                         cudaFuncAttributeMaxDynamicSharedMemorySize, (int)smem128);
    cudaFuncSetAttribute(gemm_kernel<128, true, false>,
                         cudaFuncAttributeMaxDynamicSharedMemorySize, (int)smem128);
    cudaFuncSetAttribute(gemm_kernel<64, true, true>,
                         cudaFuncAttributeMaxDynamicSharedMemorySize, (int)smem64);

    int nb256 = (n + 255) / 256;      // 196
    int EN = E + n;

    // CSR build (shared by both layers)
    detect_dtype_kernel<<<1, 32>>>((const int*)ei);
    cnt_init_kernel<<<nb256, 256>>>(cnt, n);
    cnt_count_kernel<<<(E + 255) / 256, 256>>>(cnt, ei, E);
    scan1_kernel<<<nb256, 256>>>(cnt, incl, bsum, n);
    scan2_kernel<<<1, 256>>>(bsum, nb256);
    scan3_kernel<<<nb256, 256>>>(incl, bsum, cnt, off, cursor, dinv, n);
    fill_kernel<<<(EN + 255) / 256, 256>>>(cursor, srcid, ei, E, n);

    int gemm_blocks   = (n + 63) / 64;
    int gather_blocks = (n + 7) / 8;   // 8 warps/block, warp per node

    // Layer 1: h1 = relu( Agg(x @ W1) + b1 )   (relu fused into next gemm load)
    gemm_kernel<128, false, false><<<gemm_blocks, 128, smem128>>>(x, W1, nullptr, bufA, n);
    gather_kernel<<<gather_blocks, 256>>>(bufA, bufB, srcid, off, dinv, b1, n);

    // Layer 2: h2 = relu( Agg(relu(h1) @ W2) + b2 )
    gemm_kernel<128, true, false><<<gemm_blocks, 128, smem128>>>(bufB, W2, nullptr, bufA, n);
    gather_kernel<<<gather_blocks, 256>>>(bufA, bufB, srcid, off, dinv, b2, n);

    // Head: out = relu(h2) @ Wl + bl
    gemm_kernel<64, true, true><<<gemm_blocks, 64, smem64>>>(bufB, Wl, bl, out, n);
}